// round 16
// baseline (speedup 1.0000x reference)
#include <cuda_runtime.h>
#include <cuda_bf16.h>
#include <math.h>
#include <stdint.h>

// Shapes fixed by the dataset: T=4, B=32, N=1024, C=256
#define C_DIM    256
#define T_STEPS  4
#define M_TOTAL  131072
#define M_TILE   128
#define N_CTA    1024            // M_TOTAL / M_TILE (MMA gate kernel)
#define TILE_M   64
#define NBLK     2048            // M_TOTAL / TILE_M (exact proj kernel)
#define TOTAL_EL 33554432
#define BNC      8388608
#define SWP      36              // bf16x3 smem row stride in 32-bit words
#define PLANE    (128 * SWP)     // 4608 words per plane
#define BUFW     (3 * PLANE)     // words per operand buffer (3 planes)
#define BUFB     (BUFW * 4)      // bytes per operand buffer (55296)
#define SA       260             // exact-path smem X row stride (floats)
#define W3BLK    49152           // words per (weight, nb) block: 4ch*3p*128r*32w

// ---------------- device scratch (allocation-free rule) ----------------
__device__ float    g_WTp[C_DIM * C_DIM];       // transposed Wproj [k][d]
__device__ uint32_t g_W3[4 * W3BLK];            // pre-split gate weights (packed bf16x2)
__device__ float    g_fused[TOTAL_EL];
__device__ float    g_mid[TOTAL_EL];
__device__ float    g_partial[2 * C_DIM * NBLK];
__device__ float    g_scale[C_DIM];
__device__ float    g_shift[C_DIM];

// ---------------- low-level helpers ----------------
__device__ __forceinline__ uint32_t smem_u32(const void* p) {
    uint32_t a;
    asm("{ .reg .u64 t; cvta.to.shared.u64 t, %1; cvt.u32.u64 %0, t; }"
        : "=r"(a) : "l"(p));
    return a;
}
#define CPA16(dst, src) \
    asm volatile("cp.async.cg.shared.global [%0], [%1], 16;" :: "r"(dst), "l"(src))
#define CPA_COMMIT() asm volatile("cp.async.commit_group;")
#define CPA_WAIT()   asm volatile("cp.async.wait_group 0;" ::: "memory")
#define LDSM4(r0, r1, r2, r3, addr) \
    asm volatile("ldmatrix.sync.aligned.m8n8.x4.shared.b16 {%0,%1,%2,%3}, [%4];" \
                 : "=r"(r0), "=r"(r1), "=r"(r2), "=r"(r3) : "r"(addr))

// ================= high-accuracy FMA-only sigmoid (R10 verbatim) =================
__device__ __forceinline__ float sigmoid_hi(float x) {
    float t = -x * 1.4426950408889634f;
    t = fminf(fmaxf(t, -30.0f), 30.0f);
    float fn = t + 12582912.0f;
    int ni = __float_as_int(fn) - __float_as_int(12582912.0f);
    float f = t - (fn - 12582912.0f);
    float u = f * 0.6931471805599453f;
    float p = 1.9841270e-4f;
    p = fmaf(p, u, 1.3888889e-3f);
    p = fmaf(p, u, 8.3333333e-3f);
    p = fmaf(p, u, 4.1666667e-2f);
    p = fmaf(p, u, 1.6666667e-1f);
    p = fmaf(p, u, 0.5f);
    p = fmaf(p, u, 1.0f);
    p = fmaf(p, u, 1.0f);
    float e = p * __int_as_float((ni + 127) << 23);
    float d = 1.0f + e;
    float r = __int_as_float(0x7EF311C3 - __float_as_int(d));
    r = r * fmaf(-d, r, 2.0f);
    r = r * fmaf(-d, r, 2.0f);
    r = r * fmaf(-d, r, 2.0f);
    float e2 = fmaf(-d, r, 1.0f);
    r = fmaf(r, e2, r);
    return r;
}

// ================= MMA helpers (values identical to R10..R14) =================
__device__ __forceinline__ void mma_bf16(float* d, const uint32_t* a, const uint32_t* b) {
    asm volatile(
        "mma.sync.aligned.m16n8k16.row.col.f32.bf16.bf16.f32 "
        "{%0,%1,%2,%3}, {%4,%5,%6,%7}, {%8,%9}, {%0,%1,%2,%3};"
        : "+f"(d[0]), "+f"(d[1]), "+f"(d[2]), "+f"(d[3])
        : "r"(a[0]), "r"(a[1]), "r"(a[2]), "r"(a[3]), "r"(b[0]), "r"(b[1]));
}
__device__ __forceinline__ void split3(float v, float& f1, float& f2, float& f3) {
    f1 = __bfloat162float(__float2bfloat16_rn(v));
    float r = v - f1;
    f2 = __bfloat162float(__float2bfloat16_rn(r));
    f3 = r - f2;
}
__device__ __forceinline__ uint32_t bf2(float a, float b) {
    __nv_bfloat162 t = __floats2bfloat162_rn(a, b);
    return *reinterpret_cast<uint32_t*>(&t);
}

// X split staging for chunk ch into a given buffer (R10 values verbatim).
__device__ __forceinline__ void stage_X(const float* __restrict__ Xg, int ch,
                                        uint32_t* __restrict__ sXp, int tid)
{
    const float4* X4 = (const float4*)Xg;
    #pragma unroll
    for (int i = 0; i < 8; i++) {
        int idx = tid + (i << 8);
        int r = idx >> 4, q = idx & 15;
        int w0 = r * SWP + q * 2;
        float p1, p2, p3, q1, q2, q3;
        float4 v = X4[r * 64 + ch * 16 + q];
        split3(v.x, p1, p2, p3); split3(v.y, q1, q2, q3);
        sXp[w0]             = bf2(p1, q1);
        sXp[PLANE + w0]     = bf2(p2, q2);
        sXp[2 * PLANE + w0] = bf2(p3, q3);
        split3(v.z, p1, p2, p3); split3(v.w, q1, q2, q3);
        sXp[w0 + 1]             = bf2(p1, q1);
        sXp[PLANE + w0 + 1]     = bf2(p2, q2);
        sXp[2 * PLANE + w0 + 1] = bf2(p3, q3);
    }
}

// W plane staging (pre-split) for chunk ch into a given buffer (async copy).
__device__ __forceinline__ void stage_W(const uint32_t* __restrict__ W3blk, int ch,
                                        uint32_t sW_addr, int tid)
{
    const uint32_t* wsrc = W3blk + ch * 12288;
    #pragma unroll
    for (int i = 0; i < 12; i++) {
        int idx = tid + (i << 8);            // 0..3071
        int p  = idx >> 10;
        int rw = idx & 1023;
        int r = rw >> 3, wg = rw & 7;
        uint32_t dst = sW_addr + (uint32_t)(p * PLANE + r * SWP + wg * 4) * 4u;
        CPA16(dst, wsrc + p * 4096 + r * 32 + wg * 4);
    }
}

// One chunk's MMA block: 4 k-steps, tile-outer, per-tile 6-product order
// identical to R13 (best-measured) -> per-accumulator contribution sequence
// unchanged -> identical result bits.
__device__ __forceinline__ void mma_block(uint32_t xb, uint32_t wb,
                                          const uint32_t (&Ao)[2][3],
                                          const uint32_t (&Bo)[4][3],
                                          float* __restrict__ acc)
{
    #pragma unroll
    for (int ks = 0; ks < 4; ks++) {
        const uint32_t kb = (uint32_t)ks * 32u;  // 8 words per k-step
        uint32_t A[2][3][4];
        #pragma unroll
        for (int mt = 0; mt < 2; mt++)
            #pragma unroll
            for (int p = 0; p < 3; p++)
                LDSM4(A[mt][p][0], A[mt][p][1], A[mt][p][2], A[mt][p][3],
                      xb + Ao[mt][p] + kb);
        uint32_t B[8][3][2];
        #pragma unroll
        for (int ntp = 0; ntp < 4; ntp++)
            #pragma unroll
            for (int p = 0; p < 3; p++)
                LDSM4(B[2 * ntp][p][0], B[2 * ntp][p][1],
                      B[2 * ntp + 1][p][0], B[2 * ntp + 1][p][1],
                      wb + Bo[ntp][p] + kb);
        #pragma unroll
        for (int nt = 0; nt < 8; nt++)
            #pragma unroll
            for (int mt = 0; mt < 2; mt++) {
                float* d = acc + (nt * 2 + mt) * 4;
                mma_bf16(d, A[mt][1], B[nt][1]);
                mma_bf16(d, A[mt][0], B[nt][2]);
                mma_bf16(d, A[mt][2], B[nt][0]);
                mma_bf16(d, A[mt][0], B[nt][1]);
                mma_bf16(d, A[mt][1], B[nt][0]);
                mma_bf16(d, A[mt][0], B[nt][0]);
            }
    }
}

// Dual 128x128 bf16x3 tile GEMM: acc1 = Xa @ Wa^T, acc2 = Xl @ Wl^T.
// Both GEMMs share each chunk's staging phase -> half the sync/wait phases of
// the two-pass version; per-accumulator arithmetic sequence unchanged.
__device__ __forceinline__ void gemm6_dual(const float* __restrict__ Xa,
                                           const float* __restrict__ Xl,
                                           const uint32_t* __restrict__ Wa3,
                                           const uint32_t* __restrict__ Wl3,
                                           float* __restrict__ acc1,
                                           float* __restrict__ acc2,
                                           uint32_t* __restrict__ smw,
                                           uint32_t smbase, int tid)
{
    const int lane = tid & 31, w = tid >> 5;
    const int warp_m = w & 3, warp_n = w >> 2;

    uint32_t* sXa = smw;
    uint32_t* sXl = smw + BUFW;
    const uint32_t sXa_addr = smbase;
    const uint32_t sXl_addr = smbase + BUFB;
    const uint32_t sWa_addr = smbase + 2 * BUFB;
    const uint32_t sWl_addr = smbase + 3 * BUFB;

    // ldmatrix lane offsets within a buffer (bytes) — R11 mapping verbatim
    uint32_t Ao[2][3], Bo[4][3];
    {
        int rowA = ((lane >> 3) & 1) * 8 + (lane & 7);
        int khA  = ((lane >> 4) & 1) * 4;
        int rowB = ((lane >> 4) & 1) * 8 + (lane & 7);
        int khB  = ((lane >> 3) & 1) * 4;
        #pragma unroll
        for (int mt = 0; mt < 2; mt++)
            #pragma unroll
            for (int p = 0; p < 3; p++) {
                int r = warp_m * 32 + mt * 16 + rowA;
                Ao[mt][p] = (uint32_t)(p * PLANE + r * SWP + khA) * 4u;
            }
        #pragma unroll
        for (int ntp = 0; ntp < 4; ntp++)
            #pragma unroll
            for (int p = 0; p < 3; p++) {
                int r = warp_n * 64 + ntp * 16 + rowB;
                Bo[ntp][p] = (uint32_t)(p * PLANE + r * SWP + khB) * 4u;
            }
    }

    #pragma unroll
    for (int i = 0; i < 64; i++) { acc1[i] = 0.0f; acc2[i] = 0.0f; }

    #pragma unroll 1
    for (int ch = 0; ch < 4; ch++) {
        __syncthreads();
        stage_W(Wa3, ch, sWa_addr, tid);
        stage_W(Wl3, ch, sWl_addr, tid);
        CPA_COMMIT();
        stage_X(Xa, ch, sXa, tid);
        stage_X(Xl, ch, sXl, tid);
        CPA_WAIT();
        __syncthreads();

        mma_block(sXa_addr, sWa_addr, Ao, Bo, acc1);
        mma_block(sXl_addr, sWl_addr, Ao, Bo, acc2);
    }
}

// ================= exact-path helpers (R8/R10 verbatim) =================
__device__ __forceinline__ unsigned long long pk2(float lo, float hi) {
    unsigned long long r;
    asm("mov.b64 %0, {%1, %2};" : "=l"(r) : "f"(lo), "f"(hi));
    return r;
}
__device__ __forceinline__ void upk2(unsigned long long v, float& lo, float& hi) {
    asm("mov.b64 {%0, %1}, %2;" : "=f"(lo), "=f"(hi) : "l"(v));
}
__device__ __forceinline__ void fma2(unsigned long long& d,
                                     unsigned long long a, unsigned long long b) {
    asm("fma.rn.f32x2 %0, %1, %2, %0;" : "+l"(d) : "l"(a), "l"(b));
}

// 64x256 exact tile GEMM, sequential-k fmaf chains (arithmetic verbatim)
// with double-buffered W prefetch (R12's measured-faster proj pipeline).
__device__ __forceinline__ void gemm_pass_pipe(const float* __restrict__ sX,
                                               const float* __restrict__ WT,
                                               float* __restrict__ sWf,
                                               uint32_t sW_addr,
                                               unsigned long long (&accP)[8][4],
                                               int tid)
{
    const int m0 = (tid >> 5) << 3;
    const int d0 = (tid & 31) << 3;

    #pragma unroll
    for (int i = 0; i < 8; i++)
        #pragma unroll
        for (int j = 0; j < 4; j++) accP[i][j] = 0ULL;

    // prologue: stage kc=0 into buffer 0 (caller's sA copy also in flight)
    {
        const char* src = (const char*)WT;
        #pragma unroll
        for (int i = 0; i < 8; i++) {
            int idx = tid + (i << 8);
            CPA16(sW_addr + (uint32_t)idx * 16u, src + (size_t)idx * 16);
        }
        CPA_COMMIT();
        CPA_WAIT();                       // waits sA + W0
    }
    __syncthreads();

    #pragma unroll 1
    for (int kc = 0; kc < 8; kc++) {
        const int cur = kc & 1;

        if (kc < 7) {                     // prefetch next W chunk
            const char* src = (const char*)(WT + (kc + 1) * 32 * 256);
            const uint32_t dstb = sW_addr + (uint32_t)((cur ^ 1) * 32768);
            #pragma unroll
            for (int i = 0; i < 8; i++) {
                int idx = tid + (i << 8);
                CPA16(dstb + (uint32_t)idx * 16u, src + (size_t)idx * 16);
            }
            CPA_COMMIT();
        }

        const float* sW = sWf + cur * 8192;
        #pragma unroll
        for (int kkq = 0; kkq < 8; kkq++) {
            float a_[8][4];
            #pragma unroll
            for (int i = 0; i < 8; i++)
                *(float4*)a_[i] = *(const float4*)&sX[(m0 + i) * SA + kc * 32 + kkq * 4];
            #pragma unroll
            for (int kk = 0; kk < 4; kk++) {
                const float* wr = &sW[(kkq * 4 + kk) * 256 + d0];
                float4 w0 = *(const float4*)wr;
                float4 w1 = *(const float4*)(wr + 4);
                unsigned long long b0 = pk2(w0.x, w0.y);
                unsigned long long b1 = pk2(w0.z, w0.w);
                unsigned long long b2 = pk2(w1.x, w1.y);
                unsigned long long b3 = pk2(w1.z, w1.w);
                #pragma unroll
                for (int i = 0; i < 8; i++) {
                    unsigned long long av = pk2(a_[i][kk], a_[i][kk]);
                    fma2(accP[i][0], av, b0);
                    fma2(accP[i][1], av, b1);
                    fma2(accP[i][2], av, b2);
                    fma2(accP[i][3], av, b3);
                }
            }
        }

        CPA_WAIT();
        __syncthreads();
    }
}

// ================= prep kernels (verbatim) =================
__global__ void wt_kernel(const float* __restrict__ Wproj)
{
    int k = blockIdx.x;
    int d = threadIdx.x;
    g_WTp[k * 256 + d] = Wproj[d * 256 + k];
}

__global__ void w3_kernel(const float* __restrict__ Watt,
                          const float* __restrict__ Wlsm)
{
    int idx = blockIdx.x * 256 + threadIdx.x;       // 0..131071
    int word = idx & 31;
    int row  = (idx >> 5) & 127;
    int ch   = (idx >> 12) & 3;
    int nb   = (idx >> 14) & 1;
    int wt   = (idx >> 15) & 1;
    const float* W = wt ? Wlsm : Watt;
    int rowg = nb * 128 + row;
    int k = ch * 64 + word * 2;
    float v0 = W[rowg * 256 + k];
    float v1 = W[rowg * 256 + k + 1];
    float a1, a2, a3, b1, b2, b3;
    split3(v0, a1, a2, a3);
    split3(v1, b1, b2, b3);
    uint32_t* dst = g_W3 + (size_t)(wt * 2 + nb) * W3BLK + ch * 12288 + row * 32 + word;
    dst[0]    = bf2(a1, b1);
    dst[4096] = bf2(a2, b2);
    dst[8192] = bf2(a3, b3);
}

// ================= gates on tensor cores: fused -> g_fused =================
__global__ void __launch_bounds__(256, 1)
g12_kernel(const float* __restrict__ xa, const float* __restrict__ xl,
           const float* __restrict__ batt, const float* __restrict__ blsm)
{
    extern __shared__ uint32_t smw[];
    const uint32_t smbase = smem_u32(smw);

    const int tid = threadIdx.x;
    const int lane = tid & 31, w = tid >> 5;
    const int warp_m = w & 3, warp_n = w >> 2;
    const int g = lane >> 2, tq = lane & 3;
    const size_t row0 = (size_t)blockIdx.x * M_TILE;
    const float* Xa = xa + row0 * C_DIM;
    const float* Xl = xl + row0 * C_DIM;

    #pragma unroll 1
    for (int nb = 0; nb < 2; nb++) {
        const int cbase = nb * 128 + warp_n * 64;

        // ---- dual GEMM: s1 = a@Watt^T, d2 = l@Wlsm^T (shared staging) ----
        float s1[64], d2[64];
        gemm6_dual(Xa, Xl,
                   g_W3 + (size_t)(0 * 2 + nb) * W3BLK,
                   g_W3 + (size_t)(1 * 2 + nb) * W3BLK,
                   s1, d2, smw, smbase, tid);

        // ---- gate_lsm = sigmoid(s1 + batt) (in regs) ----
        #pragma unroll
        for (int nt = 0; nt < 8; nt++) {
            float2 bA = ((const float2*)(batt + cbase))[nt * 4 + tq];
            float* d = s1 + (nt * 2) * 4;
            d[0] = sigmoid_hi(d[0] + bA.x);
            d[1] = sigmoid_hi(d[1] + bA.y);
            d[2] = sigmoid_hi(d[2] + bA.x);
            d[3] = sigmoid_hi(d[3] + bA.y);
            d = s1 + (nt * 2 + 1) * 4;
            d[0] = sigmoid_hi(d[0] + bA.x);
            d[1] = sigmoid_hi(d[1] + bA.y);
            d[2] = sigmoid_hi(d[2] + bA.x);
            d[3] = sigmoid_hi(d[3] + bA.y);
        }

        // ---- gate_attn = sigmoid(d2 + blsm); fuse; store ----
        #pragma unroll
        for (int nt = 0; nt < 8; nt++) {
            float2 bL = ((const float2*)(blsm + cbase))[nt * 4 + tq];
            int col = cbase + nt * 8 + tq * 2;
            #pragma unroll
            for (int mt = 0; mt < 2; mt++) {
                size_t r1 = row0 + warp_m * 32 + mt * 16 + g;
                const float* dd = d2 + (nt * 2 + mt) * 4;
                const float* ss = s1 + (nt * 2 + mt) * 4;
                float2 a1 = *(const float2*)(xa + r1 * C_DIM + col);
                float2 l1 = *(const float2*)(xl + r1 * C_DIM + col);
                float2 a2 = *(const float2*)(xa + (r1 + 8) * C_DIM + col);
                float2 l2 = *(const float2*)(xl + (r1 + 8) * C_DIM + col);
                float2 o1, o2;
                o1.x = a1.x * sigmoid_hi(dd[0] + bL.x) + l1.x * ss[0];
                o1.y = a1.y * sigmoid_hi(dd[1] + bL.y) + l1.y * ss[1];
                o2.x = a2.x * sigmoid_hi(dd[2] + bL.x) + l2.x * ss[2];
                o2.y = a2.y * sigmoid_hi(dd[3] + bL.y) + l2.y * ss[3];
                *(float2*)(g_fused + r1 * C_DIM + col) = o1;
                *(float2*)(g_fused + (r1 + 8) * C_DIM + col) = o2;
            }
        }
    }
}

// ================= projection on the exact R8 chain (R12 verbatim) =================
__global__ void __launch_bounds__(256, 1)
proj_kernel(const float* __restrict__ bproj)
{
    extern __shared__ float sm[];
    float* sA  = sm;                      // [64][SA]
    float* sWf = sm + 64 * SA;            // [2][32][256]
    const uint32_t sA_addr = smem_u32(sA);
    const uint32_t sW_addr = smem_u32(sWf);

    const int tid = threadIdx.x;
    const int mg = tid >> 5;
    const int m0 = mg << 3;
    const int d0 = (tid & 31) << 3;
    const size_t row0 = (size_t)blockIdx.x * TILE_M;

    // stage fused tile row-major via cp.async (pure copy, identical data)
    {
        const char* src = (const char*)(g_fused + row0 * C_DIM);
        #pragma unroll
        for (int i = 0; i < 16; i++) {
            int idx = tid + (i << 8);             // float4 index 0..4095
            int r = idx >> 6, c4 = idx & 63;
            CPA16(sA_addr + (uint32_t)(r * SA + c4 * 4) * 4u, src + (size_t)idx * 16);
        }
        CPA_COMMIT();
    }
    // (gemm_pass_pipe's prologue wait covers this group too)

    unsigned long long accP[8][4];
    gemm_pass_pipe(sA, g_WTp, sWf, sW_addr, accP, tid);

    float cs[8], cs2[8];
    #pragma unroll
    for (int j = 0; j < 8; j++) { cs[j] = 0.0f; cs2[j] = 0.0f; }
    #pragma unroll
    for (int i = 0; i < 8; i++) {
        float o[8];
        #pragma unroll
        for (int jp = 0; jp < 4; jp++)
            upk2(accP[i][jp], o[jp * 2], o[jp * 2 + 1]);
        #pragma unroll
        for (int j = 0; j < 8; j++) {
            o[j] = o[j] + bproj[d0 + j];
            cs[j]  += o[j];
            cs2[j] = fmaf(o[j], o[j], cs2[j]);
        }
        float4* dst = (float4*)&g_mid[(row0 + m0 + i) * C_DIM + d0];
        dst[0] = make_float4(o[0], o[1], o[2], o[3]);
        dst[1] = make_float4(o[4], o[5], o[6], o[7]);
    }

    // deterministic per-channel partial reduction (reuse sW buffer 0)
    __syncthreads();
    float* sRed = sWf;
    #pragma unroll
    for (int j = 0; j < 8; j++) {
        sRed[(d0 + j) * 8 + mg]        = cs[j];
        sRed[2048 + (d0 + j) * 8 + mg] = cs2[j];
    }
    __syncthreads();
    {
        int d = tid;
        float s = 0.0f, s2 = 0.0f;
        #pragma unroll
        for (int g2 = 0; g2 < 8; g2++) {
            s  += sRed[d * 8 + g2];
            s2 += sRed[2048 + d * 8 + g2];
        }
        g_partial[(size_t)d * NBLK + blockIdx.x] = s;
        g_partial[(size_t)C_DIM * NBLK + (size_t)d * NBLK + blockIdx.x] = s2;
    }
}

// ================= BN stats (fp64, deterministic) — verbatim =================
__global__ void bn_stats_kernel(const float* __restrict__ gamma,
                                const float* __restrict__ beta)
{
    __shared__ double sh0[256];
    __shared__ double sh1[256];
    int d = blockIdx.x, t = threadIdx.x;
    const float* ps = g_partial + (size_t)d * NBLK;
    const float* pq = g_partial + (size_t)C_DIM * NBLK + (size_t)d * NBLK;
    double s = 0.0, s2 = 0.0;
    for (int i = t; i < NBLK; i += 256) { s += ps[i]; s2 += pq[i]; }
    sh0[t] = s; sh1[t] = s2;
    __syncthreads();
    for (int off = 128; off > 0; off >>= 1) {
        if (t < off) { sh0[t] += sh0[t + off]; sh1[t] += sh1[t + off]; }
        __syncthreads();
    }
    if (t == 0) {
        double inv  = 1.0 / (double)M_TOTAL;
        double mean = sh0[0] * inv;
        double var  = sh1[0] * inv - mean * mean;
        float rstd = (float)(1.0 / sqrt(var + 1e-5));
        float gm = gamma[d];
        g_scale[d] = gm * rstd;
        g_shift[d] = beta[d] - (float)mean * gm * rstd;
    }
}

// ================= LIF — verbatim =================
__global__ void lif_kernel(const float* __restrict__ lifw, float* __restrict__ out)
{
    int i = (blockIdx.x * blockDim.x + threadIdx.x) << 2;
    if (i >= BNC) return;
    float ti = 1.0f / (1.0f + expf(-lifw[0]));
    int c = i & (C_DIM - 1);
    float4 sc = *(const float4*)&g_scale[c];
    float4 sf = *(const float4*)&g_shift[c];
    float v0 = 0.f, v1 = 0.f, v2 = 0.f, v3 = 0.f;
    #pragma unroll
    for (int t = 0; t < T_STEPS; t++) {
        float4 x = *(const float4*)&g_mid[(size_t)t * BNC + i];
        float y0 = fmaf(x.x, sc.x, sf.x);
        float y1 = fmaf(x.y, sc.y, sf.y);
        float y2 = fmaf(x.z, sc.z, sf.z);
        float y3 = fmaf(x.w, sc.w, sf.w);
        v0 += (y0 - v0) * ti;
        v1 += (y1 - v1) * ti;
        v2 += (y2 - v2) * ti;
        v3 += (y3 - v3) * ti;
        float s0 = (v0 >= 1.0f) ? 1.0f : 0.0f;
        float s1 = (v1 >= 1.0f) ? 1.0f : 0.0f;
        float s2 = (v2 >= 1.0f) ? 1.0f : 0.0f;
        float s3 = (v3 >= 1.0f) ? 1.0f : 0.0f;
        v0 = (s0 > 0.f) ? 0.f : v0;
        v1 = (s1 > 0.f) ? 0.f : v1;
        v2 = (s2 > 0.f) ? 0.f : v2;
        v3 = (s3 > 0.f) ? 0.f : v3;
        *(float4*)&out[(size_t)t * BNC + i] = make_float4(s0, s1, s2, s3);
    }
}

extern "C" void kernel_launch(void* const* d_in, const int* in_sizes, int n_in,
                              void* d_out, int out_size)
{
    const float* xa    = (const float*)d_in[0];
    const float* xl    = (const float*)d_in[1];
    const float* Watt  = (const float*)d_in[2];
    const float* batt  = (const float*)d_in[3];
    const float* Wlsm  = (const float*)d_in[4];
    const float* blsm  = (const float*)d_in[5];
    const float* Wproj = (const float*)d_in[6];
    const float* bproj = (const float*)d_in[7];
    const float* gamma = (const float*)d_in[8];
    const float* beta  = (const float*)d_in[9];
    const float* lifw  = (const float*)d_in[10];

    const int mma_smem  = 4 * BUFB;                                    // 221184
    const int proj_smem = (64 * SA + 2 * 32 * 256) * sizeof(float);    // 132096
    cudaFuncSetAttribute(g12_kernel,  cudaFuncAttributeMaxDynamicSharedMemorySize, mma_smem);
    cudaFuncSetAttribute(proj_kernel, cudaFuncAttributeMaxDynamicSharedMemorySize, proj_smem);

    wt_kernel<<<C_DIM, 256>>>(Wproj);
    w3_kernel<<<512, 256>>>(Watt, Wlsm);
    g12_kernel<<<N_CTA, 256, mma_smem>>>(xa, xl, batt, blsm);
    proj_kernel<<<NBLK, 256, proj_smem>>>(bproj);
    bn_stats_kernel<<<C_DIM, 256>>>(gamma, beta);
    lif_kernel<<<BNC / 4 / 256, 256>>>(lifw, (float*)d_out);
}

// round 17
// speedup vs baseline: 1.0743x; 1.0743x over previous
#include <cuda_runtime.h>
#include <cuda_bf16.h>
#include <math.h>
#include <stdint.h>

// Shapes fixed by the dataset: T=4, B=32, N=1024, C=256
#define C_DIM    256
#define T_STEPS  4
#define M_TOTAL  131072
#define M_TILE   128
#define N_CTA    1024            // M_TOTAL / M_TILE (MMA gate kernel)
#define TILE_M   64
#define NBLK     2048            // M_TOTAL / TILE_M (exact proj kernel)
#define TOTAL_EL 33554432
#define BNC      8388608
#define SWP      36              // bf16x3 smem row stride in 32-bit words
#define PLANE    (128 * SWP)     // 4608 words per plane
#define SA       260             // exact-path smem X row stride (floats)
#define W3BLK    49152           // words per (weight, nb) block: 4ch*3p*128r*32w

// ---------------- device scratch (allocation-free rule) ----------------
__device__ float    g_WTp[C_DIM * C_DIM];       // transposed Wproj [k][d]
__device__ uint32_t g_W3[4 * W3BLK];            // pre-split gate weights (packed bf16x2)
__device__ float    g_fused[TOTAL_EL];
__device__ float    g_mid[TOTAL_EL];
__device__ float    g_partial[2 * C_DIM * NBLK];
__device__ float    g_scale[C_DIM];
__device__ float    g_shift[C_DIM];

// ---------------- low-level helpers ----------------
__device__ __forceinline__ uint32_t smem_u32(const void* p) {
    uint32_t a;
    asm("{ .reg .u64 t; cvta.to.shared.u64 t, %1; cvt.u32.u64 %0, t; }"
        : "=r"(a) : "l"(p));
    return a;
}
#define CPA16(dst, src) \
    asm volatile("cp.async.cg.shared.global [%0], [%1], 16;" :: "r"(dst), "l"(src))
#define CPA_COMMIT() asm volatile("cp.async.commit_group;")
#define CPA_WAIT()   asm volatile("cp.async.wait_group 0;" ::: "memory")
#define LDSM4(r0, r1, r2, r3, addr) \
    asm volatile("ldmatrix.sync.aligned.m8n8.x4.shared.b16 {%0,%1,%2,%3}, [%4];" \
                 : "=r"(r0), "=r"(r1), "=r"(r2), "=r"(r3) : "r"(addr))

// ================= high-accuracy FMA-only sigmoid (R10 verbatim) =================
__device__ __forceinline__ float sigmoid_hi(float x) {
    float t = -x * 1.4426950408889634f;
    t = fminf(fmaxf(t, -30.0f), 30.0f);
    float fn = t + 12582912.0f;
    int ni = __float_as_int(fn) - __float_as_int(12582912.0f);
    float f = t - (fn - 12582912.0f);
    float u = f * 0.6931471805599453f;
    float p = 1.9841270e-4f;
    p = fmaf(p, u, 1.3888889e-3f);
    p = fmaf(p, u, 8.3333333e-3f);
    p = fmaf(p, u, 4.1666667e-2f);
    p = fmaf(p, u, 1.6666667e-1f);
    p = fmaf(p, u, 0.5f);
    p = fmaf(p, u, 1.0f);
    p = fmaf(p, u, 1.0f);
    float e = p * __int_as_float((ni + 127) << 23);
    float d = 1.0f + e;
    float r = __int_as_float(0x7EF311C3 - __float_as_int(d));
    r = r * fmaf(-d, r, 2.0f);
    r = r * fmaf(-d, r, 2.0f);
    r = r * fmaf(-d, r, 2.0f);
    float e2 = fmaf(-d, r, 1.0f);
    r = fmaf(r, e2, r);
    return r;
}

// ================= MMA helpers (values identical to R10..R16) =================
__device__ __forceinline__ void mma_bf16(float* d, const uint32_t* a, const uint32_t* b) {
    asm volatile(
        "mma.sync.aligned.m16n8k16.row.col.f32.bf16.bf16.f32 "
        "{%0,%1,%2,%3}, {%4,%5,%6,%7}, {%8,%9}, {%0,%1,%2,%3};"
        : "+f"(d[0]), "+f"(d[1]), "+f"(d[2]), "+f"(d[3])
        : "r"(a[0]), "r"(a[1]), "r"(a[2]), "r"(a[3]), "r"(b[0]), "r"(b[1]));
}
__device__ __forceinline__ void split3(float v, float& f1, float& f2, float& f3) {
    f1 = __bfloat162float(__float2bfloat16_rn(v));
    float r = v - f1;
    f2 = __bfloat162float(__float2bfloat16_rn(r));
    f3 = r - f2;
}
__device__ __forceinline__ uint32_t bf2(float a, float b) {
    __nv_bfloat162 t = __floats2bfloat162_rn(a, b);
    return *reinterpret_cast<uint32_t*>(&t);
}

// 128x128 = X[128,256] @ Wblk[128,256]^T in bf16x3 (6 products).
// R13 structure/arithmetic with 512 threads (16 warps): each warp owns
// 32 rows x 32 cols (2 mt x 4 nt tiles). Same split values, same LDSM byte->
// register mapping, same per-accumulator product/k order -> identical bits.
__device__ __forceinline__ void gemm6_ld(const float* __restrict__ Xg,
                                         const uint32_t* __restrict__ W3blk,
                                         float* __restrict__ acc,   // [32]
                                         uint32_t* __restrict__ sXp,
                                         uint32_t sX_addr, uint32_t sW_addr,
                                         int tid)
{
    const int lane = tid & 31, w = tid >> 5;
    const int warp_m = w & 3, warp_n = w >> 2;   // 4 x 4 warp grid

    // ldmatrix lane-address bases (byte addresses) — mapping verbatim
    uint32_t Ab[2][3], Bb[2][3];
    {
        int rowA = ((lane >> 3) & 1) * 8 + (lane & 7);
        int khA  = ((lane >> 4) & 1) * 4;            // words
        int rowB = ((lane >> 4) & 1) * 8 + (lane & 7);
        int khB  = ((lane >> 3) & 1) * 4;
        #pragma unroll
        for (int mt = 0; mt < 2; mt++)
            #pragma unroll
            for (int p = 0; p < 3; p++) {
                int r = warp_m * 32 + mt * 16 + rowA;
                Ab[mt][p] = sX_addr + (uint32_t)(p * PLANE + r * SWP + khA) * 4u;
            }
        #pragma unroll
        for (int ntp = 0; ntp < 2; ntp++)
            #pragma unroll
            for (int p = 0; p < 3; p++) {
                int r = warp_n * 32 + ntp * 16 + rowB;
                Bb[ntp][p] = sW_addr + (uint32_t)(p * PLANE + r * SWP + khB) * 4u;
            }
    }

    #pragma unroll
    for (int i = 0; i < 32; i++) acc[i] = 0.0f;

    #pragma unroll 1
    for (int ch = 0; ch < 4; ch++) {
        __syncthreads();
        // ---- W staging: async copy of pre-split planes (512 threads) ----
        {
            const uint32_t* wsrc = W3blk + ch * 12288;
            #pragma unroll
            for (int i = 0; i < 6; i++) {
                int idx = tid + (i << 9);            // 0..3071
                int p  = idx >> 10;
                int rw = idx & 1023;
                int r = rw >> 3, wg = rw & 7;
                uint32_t dst = sW_addr + (uint32_t)(p * PLANE + r * SWP + wg * 4) * 4u;
                CPA16(dst, wsrc + p * 4096 + r * 32 + wg * 4);
            }
            CPA_COMMIT();
        }
        // ---- X staging: split3 in-kernel (values verbatim; 512 threads) ----
        {
            const float4* X4 = (const float4*)Xg;
            #pragma unroll
            for (int i = 0; i < 4; i++) {
                int idx = tid + (i << 9);            // 0..2047
                int r = idx >> 4, q = idx & 15;
                int w0 = r * SWP + q * 2;
                float p1, p2, p3, q1, q2, q3;
                float4 v = X4[r * 64 + ch * 16 + q];
                split3(v.x, p1, p2, p3); split3(v.y, q1, q2, q3);
                sXp[w0]             = bf2(p1, q1);
                sXp[PLANE + w0]     = bf2(p2, q2);
                sXp[2 * PLANE + w0] = bf2(p3, q3);
                split3(v.z, p1, p2, p3); split3(v.w, q1, q2, q3);
                sXp[w0 + 1]             = bf2(p1, q1);
                sXp[PLANE + w0 + 1]     = bf2(p2, q2);
                sXp[2 * PLANE + w0 + 1] = bf2(p3, q3);
            }
        }
        CPA_WAIT();
        __syncthreads();

        #pragma unroll
        for (int ks = 0; ks < 4; ks++) {
            const uint32_t kb = (uint32_t)ks * 32u;  // 8 words per k-step
            uint32_t A[2][3][4];
            #pragma unroll
            for (int mt = 0; mt < 2; mt++)
                #pragma unroll
                for (int p = 0; p < 3; p++)
                    LDSM4(A[mt][p][0], A[mt][p][1], A[mt][p][2], A[mt][p][3],
                          Ab[mt][p] + kb);
            uint32_t B[4][3][2];
            #pragma unroll
            for (int ntp = 0; ntp < 2; ntp++)
                #pragma unroll
                for (int p = 0; p < 3; p++)
                    LDSM4(B[2 * ntp][p][0], B[2 * ntp][p][1],
                          B[2 * ntp + 1][p][0], B[2 * ntp + 1][p][1],
                          Bb[ntp][p] + kb);
            #pragma unroll
            for (int nt = 0; nt < 4; nt++)
                #pragma unroll
                for (int mt = 0; mt < 2; mt++) {
                    float* d = acc + (nt * 2 + mt) * 4;
                    mma_bf16(d, A[mt][1], B[nt][1]);
                    mma_bf16(d, A[mt][0], B[nt][2]);
                    mma_bf16(d, A[mt][2], B[nt][0]);
                    mma_bf16(d, A[mt][0], B[nt][1]);
                    mma_bf16(d, A[mt][1], B[nt][0]);
                    mma_bf16(d, A[mt][0], B[nt][0]);
                }
        }
    }
}

// ================= exact-path helpers (R8/R10 verbatim) =================
__device__ __forceinline__ unsigned long long pk2(float lo, float hi) {
    unsigned long long r;
    asm("mov.b64 %0, {%1, %2};" : "=l"(r) : "f"(lo), "f"(hi));
    return r;
}
__device__ __forceinline__ void upk2(unsigned long long v, float& lo, float& hi) {
    asm("mov.b64 {%0, %1}, %2;" : "=f"(lo), "=f"(hi) : "l"(v));
}
__device__ __forceinline__ void fma2(unsigned long long& d,
                                     unsigned long long a, unsigned long long b) {
    asm("fma.rn.f32x2 %0, %1, %2, %0;" : "+l"(d) : "l"(a), "l"(b));
}

// 64x256 exact tile GEMM, sequential-k fmaf chains (arithmetic verbatim)
// with double-buffered W prefetch (R12's measured-faster proj pipeline).
__device__ __forceinline__ void gemm_pass_pipe(const float* __restrict__ sX,
                                               const float* __restrict__ WT,
                                               float* __restrict__ sWf,
                                               uint32_t sW_addr,
                                               unsigned long long (&accP)[8][4],
                                               int tid)
{
    const int m0 = (tid >> 5) << 3;
    const int d0 = (tid & 31) << 3;

    #pragma unroll
    for (int i = 0; i < 8; i++)
        #pragma unroll
        for (int j = 0; j < 4; j++) accP[i][j] = 0ULL;

    // prologue: stage kc=0 into buffer 0 (caller's sA copy also in flight)
    {
        const char* src = (const char*)WT;
        #pragma unroll
        for (int i = 0; i < 8; i++) {
            int idx = tid + (i << 8);
            CPA16(sW_addr + (uint32_t)idx * 16u, src + (size_t)idx * 16);
        }
        CPA_COMMIT();
        CPA_WAIT();                       // waits sA + W0
    }
    __syncthreads();

    #pragma unroll 1
    for (int kc = 0; kc < 8; kc++) {
        const int cur = kc & 1;

        if (kc < 7) {                     // prefetch next W chunk
            const char* src = (const char*)(WT + (kc + 1) * 32 * 256);
            const uint32_t dstb = sW_addr + (uint32_t)((cur ^ 1) * 32768);
            #pragma unroll
            for (int i = 0; i < 8; i++) {
                int idx = tid + (i << 8);
                CPA16(dstb + (uint32_t)idx * 16u, src + (size_t)idx * 16);
            }
            CPA_COMMIT();
        }

        const float* sW = sWf + cur * 8192;
        #pragma unroll
        for (int kkq = 0; kkq < 8; kkq++) {
            float a_[8][4];
            #pragma unroll
            for (int i = 0; i < 8; i++)
                *(float4*)a_[i] = *(const float4*)&sX[(m0 + i) * SA + kc * 32 + kkq * 4];
            #pragma unroll
            for (int kk = 0; kk < 4; kk++) {
                const float* wr = &sW[(kkq * 4 + kk) * 256 + d0];
                float4 w0 = *(const float4*)wr;
                float4 w1 = *(const float4*)(wr + 4);
                unsigned long long b0 = pk2(w0.x, w0.y);
                unsigned long long b1 = pk2(w0.z, w0.w);
                unsigned long long b2 = pk2(w1.x, w1.y);
                unsigned long long b3 = pk2(w1.z, w1.w);
                #pragma unroll
                for (int i = 0; i < 8; i++) {
                    unsigned long long av = pk2(a_[i][kk], a_[i][kk]);
                    fma2(accP[i][0], av, b0);
                    fma2(accP[i][1], av, b1);
                    fma2(accP[i][2], av, b2);
                    fma2(accP[i][3], av, b3);
                }
            }
        }

        CPA_WAIT();
        __syncthreads();
    }
}

// ================= prep kernels (verbatim) =================
__global__ void wt_kernel(const float* __restrict__ Wproj)
{
    int k = blockIdx.x;
    int d = threadIdx.x;
    g_WTp[k * 256 + d] = Wproj[d * 256 + k];
}

__global__ void w3_kernel(const float* __restrict__ Watt,
                          const float* __restrict__ Wlsm)
{
    int idx = blockIdx.x * 256 + threadIdx.x;       // 0..131071
    int word = idx & 31;
    int row  = (idx >> 5) & 127;
    int ch   = (idx >> 12) & 3;
    int nb   = (idx >> 14) & 1;
    int wt   = (idx >> 15) & 1;
    const float* W = wt ? Wlsm : Watt;
    int rowg = nb * 128 + row;
    int k = ch * 64 + word * 2;
    float v0 = W[rowg * 256 + k];
    float v1 = W[rowg * 256 + k + 1];
    float a1, a2, a3, b1, b2, b3;
    split3(v0, a1, a2, a3);
    split3(v1, b1, b2, b3);
    uint32_t* dst = g_W3 + (size_t)(wt * 2 + nb) * W3BLK + ch * 12288 + row * 32 + word;
    dst[0]    = bf2(a1, b1);
    dst[4096] = bf2(a2, b2);
    dst[8192] = bf2(a3, b3);
}

// ================= gates on tensor cores: fused -> g_fused (512 thr) =========
__global__ void __launch_bounds__(512, 1)
g12_kernel(const float* __restrict__ xa, const float* __restrict__ xl,
           const float* __restrict__ batt, const float* __restrict__ blsm)
{
    extern __shared__ uint32_t smw[];
    uint32_t* sX = smw;
    uint32_t* sW = smw + 3 * PLANE;
    const uint32_t sX_addr = smem_u32(sX);
    const uint32_t sW_addr = smem_u32(sW);

    const int tid = threadIdx.x;
    const int lane = tid & 31, w = tid >> 5;
    const int warp_m = w & 3, warp_n = w >> 2;   // 4 x 4
    const int g = lane >> 2, tq = lane & 3;
    const size_t row0 = (size_t)blockIdx.x * M_TILE;
    const float* Xa = xa + row0 * C_DIM;
    const float* Xl = xl + row0 * C_DIM;

    #pragma unroll 1
    for (int nb = 0; nb < 2; nb++) {
        const int cbase = nb * 128 + warp_n * 32;

        // ---- pass 1: gate_lsm = sigmoid(a @ Watt^T + batt) (in regs) ----
        float s1[32];
        gemm6_ld(Xa, g_W3 + (size_t)(0 * 2 + nb) * W3BLK, s1, sX, sX_addr, sW_addr, tid);
        #pragma unroll
        for (int nt = 0; nt < 4; nt++) {
            float2 bA = ((const float2*)(batt + cbase))[nt * 4 + tq];
            float* d = s1 + (nt * 2) * 4;
            d[0] = sigmoid_hi(d[0] + bA.x);
            d[1] = sigmoid_hi(d[1] + bA.y);
            d[2] = sigmoid_hi(d[2] + bA.x);
            d[3] = sigmoid_hi(d[3] + bA.y);
            d = s1 + (nt * 2 + 1) * 4;
            d[0] = sigmoid_hi(d[0] + bA.x);
            d[1] = sigmoid_hi(d[1] + bA.y);
            d[2] = sigmoid_hi(d[2] + bA.x);
            d[3] = sigmoid_hi(d[3] + bA.y);
        }

        // ---- pass 2: gate_attn = sigmoid(l @ Wlsm^T + blsm); fuse; store ----
        float d2[32];
        gemm6_ld(Xl, g_W3 + (size_t)(1 * 2 + nb) * W3BLK, d2, sX, sX_addr, sW_addr, tid);

        #pragma unroll
        for (int nt = 0; nt < 4; nt++) {
            float2 bL = ((const float2*)(blsm + cbase))[nt * 4 + tq];
            int col = cbase + nt * 8 + tq * 2;
            #pragma unroll
            for (int mt = 0; mt < 2; mt++) {
                size_t r1 = row0 + warp_m * 32 + mt * 16 + g;
                const float* dd = d2 + (nt * 2 + mt) * 4;
                const float* ss = s1 + (nt * 2 + mt) * 4;
                float2 a1 = *(const float2*)(xa + r1 * C_DIM + col);
                float2 l1 = *(const float2*)(xl + r1 * C_DIM + col);
                float2 a2 = *(const float2*)(xa + (r1 + 8) * C_DIM + col);
                float2 l2 = *(const float2*)(xl + (r1 + 8) * C_DIM + col);
                float2 o1, o2;
                o1.x = a1.x * sigmoid_hi(dd[0] + bL.x) + l1.x * ss[0];
                o1.y = a1.y * sigmoid_hi(dd[1] + bL.y) + l1.y * ss[1];
                o2.x = a2.x * sigmoid_hi(dd[2] + bL.x) + l2.x * ss[2];
                o2.y = a2.y * sigmoid_hi(dd[3] + bL.y) + l2.y * ss[3];
                *(float2*)(g_fused + r1 * C_DIM + col) = o1;
                *(float2*)(g_fused + (r1 + 8) * C_DIM + col) = o2;
            }
        }
    }
}

// ================= projection on the exact R8 chain (R12 verbatim) =================
__global__ void __launch_bounds__(256, 1)
proj_kernel(const float* __restrict__ bproj)
{
    extern __shared__ float sm[];
    float* sA  = sm;                      // [64][SA]
    float* sWf = sm + 64 * SA;            // [2][32][256]
    const uint32_t sA_addr = smem_u32(sA);
    const uint32_t sW_addr = smem_u32(sWf);

    const int tid = threadIdx.x;
    const int mg = tid >> 5;
    const int m0 = mg << 3;
    const int d0 = (tid & 31) << 3;
    const size_t row0 = (size_t)blockIdx.x * TILE_M;

    // stage fused tile row-major via cp.async (pure copy, identical data)
    {
        const char* src = (const char*)(g_fused + row0 * C_DIM);
        #pragma unroll
        for (int i = 0; i < 16; i++) {
            int idx = tid + (i << 8);             // float4 index 0..4095
            int r = idx >> 6, c4 = idx & 63;
            CPA16(sA_addr + (uint32_t)(r * SA + c4 * 4) * 4u, src + (size_t)idx * 16);
        }
        CPA_COMMIT();
    }
    // (gemm_pass_pipe's prologue wait covers this group too)

    unsigned long long accP[8][4];
    gemm_pass_pipe(sA, g_WTp, sWf, sW_addr, accP, tid);

    float cs[8], cs2[8];
    #pragma unroll
    for (int j = 0; j < 8; j++) { cs[j] = 0.0f; cs2[j] = 0.0f; }
    #pragma unroll
    for (int i = 0; i < 8; i++) {
        float o[8];
        #pragma unroll
        for (int jp = 0; jp < 4; jp++)
            upk2(accP[i][jp], o[jp * 2], o[jp * 2 + 1]);
        #pragma unroll
        for (int j = 0; j < 8; j++) {
            o[j] = o[j] + bproj[d0 + j];
            cs[j]  += o[j];
            cs2[j] = fmaf(o[j], o[j], cs2[j]);
        }
        float4* dst = (float4*)&g_mid[(row0 + m0 + i) * C_DIM + d0];
        dst[0] = make_float4(o[0], o[1], o[2], o[3]);
        dst[1] = make_float4(o[4], o[5], o[6], o[7]);
    }

    // deterministic per-channel partial reduction (reuse sW buffer 0)
    __syncthreads();
    float* sRed = sWf;
    #pragma unroll
    for (int j = 0; j < 8; j++) {
        sRed[(d0 + j) * 8 + mg]        = cs[j];
        sRed[2048 + (d0 + j) * 8 + mg] = cs2[j];
    }
    __syncthreads();
    {
        int d = tid;
        float s = 0.0f, s2 = 0.0f;
        #pragma unroll
        for (int g2 = 0; g2 < 8; g2++) {
            s  += sRed[d * 8 + g2];
            s2 += sRed[2048 + d * 8 + g2];
        }
        g_partial[(size_t)d * NBLK + blockIdx.x] = s;
        g_partial[(size_t)C_DIM * NBLK + (size_t)d * NBLK + blockIdx.x] = s2;
    }
}

// ================= BN stats (fp64, deterministic) — verbatim =================
__global__ void bn_stats_kernel(const float* __restrict__ gamma,
                                const float* __restrict__ beta)
{
    __shared__ double sh0[256];
    __shared__ double sh1[256];
    int d = blockIdx.x, t = threadIdx.x;
    const float* ps = g_partial + (size_t)d * NBLK;
    const float* pq = g_partial + (size_t)C_DIM * NBLK + (size_t)d * NBLK;
    double s = 0.0, s2 = 0.0;
    for (int i = t; i < NBLK; i += 256) { s += ps[i]; s2 += pq[i]; }
    sh0[t] = s; sh1[t] = s2;
    __syncthreads();
    for (int off = 128; off > 0; off >>= 1) {
        if (t < off) { sh0[t] += sh0[t + off]; sh1[t] += sh1[t + off]; }
        __syncthreads();
    }
    if (t == 0) {
        double inv  = 1.0 / (double)M_TOTAL;
        double mean = sh0[0] * inv;
        double var  = sh1[0] * inv - mean * mean;
        float rstd = (float)(1.0 / sqrt(var + 1e-5));
        float gm = gamma[d];
        g_scale[d] = gm * rstd;
        g_shift[d] = beta[d] - (float)mean * gm * rstd;
    }
}

// ================= LIF — verbatim =================
__global__ void lif_kernel(const float* __restrict__ lifw, float* __restrict__ out)
{
    int i = (blockIdx.x * blockDim.x + threadIdx.x) << 2;
    if (i >= BNC) return;
    float ti = 1.0f / (1.0f + expf(-lifw[0]));
    int c = i & (C_DIM - 1);
    float4 sc = *(const float4*)&g_scale[c];
    float4 sf = *(const float4*)&g_shift[c];
    float v0 = 0.f, v1 = 0.f, v2 = 0.f, v3 = 0.f;
    #pragma unroll
    for (int t = 0; t < T_STEPS; t++) {
        float4 x = *(const float4*)&g_mid[(size_t)t * BNC + i];
        float y0 = fmaf(x.x, sc.x, sf.x);
        float y1 = fmaf(x.y, sc.y, sf.y);
        float y2 = fmaf(x.z, sc.z, sf.z);
        float y3 = fmaf(x.w, sc.w, sf.w);
        v0 += (y0 - v0) * ti;
        v1 += (y1 - v1) * ti;
        v2 += (y2 - v2) * ti;
        v3 += (y3 - v3) * ti;
        float s0 = (v0 >= 1.0f) ? 1.0f : 0.0f;
        float s1 = (v1 >= 1.0f) ? 1.0f : 0.0f;
        float s2 = (v2 >= 1.0f) ? 1.0f : 0.0f;
        float s3 = (v3 >= 1.0f) ? 1.0f : 0.0f;
        v0 = (s0 > 0.f) ? 0.f : v0;
        v1 = (s1 > 0.f) ? 0.f : v1;
        v2 = (s2 > 0.f) ? 0.f : v2;
        v3 = (s3 > 0.f) ? 0.f : v3;
        *(float4*)&out[(size_t)t * BNC + i] = make_float4(s0, s1, s2, s3);
    }
}

extern "C" void kernel_launch(void* const* d_in, const int* in_sizes, int n_in,
                              void* d_out, int out_size)
{
    const float* xa    = (const float*)d_in[0];
    const float* xl    = (const float*)d_in[1];
    const float* Watt  = (const float*)d_in[2];
    const float* batt  = (const float*)d_in[3];
    const float* Wlsm  = (const float*)d_in[4];
    const float* blsm  = (const float*)d_in[5];
    const float* Wproj = (const float*)d_in[6];
    const float* bproj = (const float*)d_in[7];
    const float* gamma = (const float*)d_in[8];
    const float* beta  = (const float*)d_in[9];
    const float* lifw  = (const float*)d_in[10];

    const int mma_smem  = 6 * PLANE * 4;                               // 110592
    const int proj_smem = (64 * SA + 2 * 32 * 256) * sizeof(float);    // 132096
    cudaFuncSetAttribute(g12_kernel,  cudaFuncAttributeMaxDynamicSharedMemorySize, mma_smem);
    cudaFuncSetAttribute(proj_kernel, cudaFuncAttributeMaxDynamicSharedMemorySize, proj_smem);

    wt_kernel<<<C_DIM, 256>>>(Wproj);
    w3_kernel<<<512, 256>>>(Watt, Wlsm);
    g12_kernel<<<N_CTA, 512, mma_smem>>>(xa, xl, batt, blsm);
    proj_kernel<<<NBLK, 256, proj_smem>>>(bproj);
    bn_stats_kernel<<<C_DIM, 256>>>(gamma, beta);
    lif_kernel<<<BNC / 4 / 256, 256>>>(lifw, (float*)d_out);
}